// round 4
// baseline (speedup 1.0000x reference)
#include <cuda_runtime.h>
#include <cstdint>

#define N_DAGS  16384
#define N_PAIRS (N_DAGS / 2)
#define N_NODES 48
#define DF      62
#define NCLS    500
#define K2B     256     // pooling partial blocks (16384/64)

typedef unsigned long long ull;

// ---------------- scratch (no cudaMalloc allowed) ----------------
__device__ float g_last   [N_DAGS * 64];
__device__ float g_score  [N_DAGS];
__device__ float g_partP  [K2B * 64];
__device__ float g_partS  [K2B];
__device__ float g_partM  [K2B];

// ---------------- packed f32x2 helpers ----------------
__device__ __forceinline__ ull ffma2(ull a, ull b, ull c) {
    ull d;
    asm("fma.rn.f32x2 %0, %1, %2, %3;" : "=l"(d) : "l"(a), "l"(b), "l"(c));
    return d;
}
__device__ __forceinline__ ull pack2(float a, float b) {
    return (ull)__float_as_uint(a) | ((ull)__float_as_uint(b) << 32);
}
__device__ __forceinline__ float lo2(ull v) { return __uint_as_float((unsigned)v); }
__device__ __forceinline__ float hi2(ull v) { return __uint_as_float((unsigned)(v >> 32)); }

__device__ __forceinline__ float warp_sum(float v) {
    #pragma unroll
    for (int o = 16; o > 0; o >>= 1) v += __shfl_xor_sync(0xffffffffu, v, o);
    return v;
}

// Per-DAG smem region layout (floats). Region base must be 128B-aligned:
//   outs  @ 0      (48*64)            rows % 128B == 0
//   xs    @ 3076   byte 12304 -> mod 128 = 16   (disjoint banks vs atoms rows)
//   atoms @ 3168   byte 12672 -> mod 128 = 0
//   preds @ 6240   (48*4 ints, 16B aligned)
//   scoreP@ 6432   (48*4 floats: per-warp score partials per node)
#define OFF_XS     3076
#define OFF_ATOMS  3168
#define OFF_PREDS  6240
#define OFF_SCOREP 6432
#define DAG_STRIDE 6624            // bytes 26496, multiple of 128

// =================================================================
// K1: recurrent DAG forward. 128 threads, TWO DAGs per block.
// Thread t: g = t>>1 (output row), h = t&1 (k-half). Merge weights in regs.
// Node scores produced as per-warp partials during the matvec phase.
// 2 barriers per step (covering both DAGs).
// =================================================================
__global__ void __launch_bounds__(128, 4)
k_dag(const float* __restrict__ atoms, const int* __restrict__ preds,
      const float* __restrict__ Wm,   const float* __restrict__ bmerge,
      const float* __restrict__ attw, const float* __restrict__ dagw,
      const float* __restrict__ Ws,   const float* __restrict__ bs) {
    extern __shared__ float smraw[];
    float* smbase = (float*)((((uintptr_t)smraw) + 127) & ~(uintptr_t)127);
    float* RA = smbase;
    float* RB = smbase + DAG_STRIDE;

    const int tid  = threadIdx.x;
    const int lane = tid & 31;
    const int warp = tid >> 5;
    const int g    = tid >> 1;   // output row (g<62 active)
    const int h    = tid & 1;    // k-half

    const float dagw_lo = dagw[lane];
    const float dagw_hi = (lane < DF - 32) ? dagw[lane + 32] : 0.f;
    const float attw_g  = (g < DF) ? attw[g] : 0.f;
    const float bm      = (g < DF) ? bmerge[g] : 0.f;
    const float bsg     = (g < DF) ? bs[g]     : 0.f;

    // merge weights: 31 packed pairs over local kk in [0,62), + 1 zero pad
    ull W2[32];
    #pragma unroll
    for (int j = 0; j < 32; j++) {
        float w0 = 0.f, w1 = 0.f;
        if (g < DF && j < 31) {
            int k0 = h * DF + 2 * j;
            w0 = Wm[g * 124 + k0];
            w1 = Wm[g * 124 + k0 + 1];
        }
        W2[j] = pack2(w0, w1);
    }
    if (tid < 2) { RA[OFF_XS + 62 + tid] = 0.f; RB[OFF_XS + 62 + tid] = 0.f; }

    for (int pr = blockIdx.x; pr < N_PAIRS; pr += gridDim.x) {
        const int dA = 2 * pr, dB = 2 * pr + 1;
        // ---- preload both DAG tiles ----
        {
            const float* AdA = atoms + (size_t)dA * N_NODES * DF;
            const float* AdB = atoms + (size_t)dB * N_NODES * DF;
            for (int idx = tid; idx < N_NODES * 64; idx += 128) {
                int n = idx >> 6, c = idx & 63;
                RA[OFF_ATOMS + idx] = (c < DF) ? AdA[n * DF + c] : 0.f;
                RB[OFF_ATOMS + idx] = (c < DF) ? AdB[n * DF + c] : 0.f;
            }
            const int* PdA = preds + (size_t)dA * N_NODES * 4;
            const int* PdB = preds + (size_t)dB * N_NODES * 4;
            int* pA = (int*)(RA + OFF_PREDS);
            int* pB = (int*)(RB + OFF_PREDS);
            for (int idx = tid; idx < N_NODES * 4; idx += 128) {
                pA[idx] = PdA[idx];
                pB[idx] = PdB[idx];
            }
        }
        __syncthreads();

        // ---- t = 0: single path, both DAGs (always pred-less) ----
        #pragma unroll
        for (int r = 0; r < 2; r++) {
            float* R = r ? RB : RA;
            float acc = 0.f;
            if (g < DF) {
                const float* wrow = Ws + g * DF + 31 * h;
                const float* xr   = R + OFF_ATOMS + 31 * h;
                #pragma unroll
                for (int f = 0; f < 31; f++) acc = fmaf(__ldg(wrow + f), xr[f], acc);
            }
            float sum = acc + __shfl_xor_sync(0xffffffffu, acc, 1);
            float val = fmaxf(sum + bsg, 0.f);
            if (h == 0 && g < DF) R[g] = val;
            float c = (h == 0) ? val * attw_g : 0.f;
            c = warp_sum(c);
            if (lane == 0) R[OFF_SCOREP + warp] = c;
        }
        __syncthreads();

        for (int t = 1; t < N_NODES; t++) {
            // ================== PHASE A: softmax + aggregate ==================
            bool anyA, anyB;
            int4 pA4, pB4;
            {
                pA4 = *(const int4*)((int*)(RA + OFF_PREDS) + t * 4);
                const bool v0 = pA4.x >= 0, v1 = pA4.y >= 0, v2 = pA4.z >= 0, v3 = pA4.w >= 0;
                anyA = v0 | v1 | v2 | v3;
                if (anyA) {
                    const float* SP = RA + OFF_SCOREP;
                    float s0 = v0 ? (SP[pA4.x*4] + SP[pA4.x*4+1] + SP[pA4.x*4+2] + SP[pA4.x*4+3]) : -1e30f;
                    float s1 = v1 ? (SP[pA4.y*4] + SP[pA4.y*4+1] + SP[pA4.y*4+2] + SP[pA4.y*4+3]) : -1e30f;
                    float s2 = v2 ? (SP[pA4.z*4] + SP[pA4.z*4+1] + SP[pA4.z*4+2] + SP[pA4.z*4+3]) : -1e30f;
                    float s3 = v3 ? (SP[pA4.w*4] + SP[pA4.w*4+1] + SP[pA4.w*4+2] + SP[pA4.w*4+3]) : -1e30f;
                    float m = fmaxf(fmaxf(s0, s1), fmaxf(s2, s3));
                    float e0 = v0 ? __expf(s0 - m) : 0.f;
                    float e1 = v1 ? __expf(s1 - m) : 0.f;
                    float e2 = v2 ? __expf(s2 - m) : 0.f;
                    float e3 = v3 ? __expf(s3 - m) : 0.f;
                    float inv = 1.f / (e0 + e1 + e2 + e3);
                    if (tid < DF) {
                        int q0 = max(pA4.x, 0), q1 = max(pA4.y, 0), q2 = max(pA4.z, 0), q3 = max(pA4.w, 0);
                        float agg = e0 * RA[q0 * 64 + tid];
                        agg = fmaf(e1, RA[q1 * 64 + tid], agg);
                        agg = fmaf(e2, RA[q2 * 64 + tid], agg);
                        agg = fmaf(e3, RA[q3 * 64 + tid], agg);
                        RA[OFF_XS + tid] = agg * inv;
                    }
                }
            }
            {
                pB4 = *(const int4*)((int*)(RB + OFF_PREDS) + t * 4);
                const bool v0 = pB4.x >= 0, v1 = pB4.y >= 0, v2 = pB4.z >= 0, v3 = pB4.w >= 0;
                anyB = v0 | v1 | v2 | v3;
                if (anyB) {
                    const float* SP = RB + OFF_SCOREP;
                    float s0 = v0 ? (SP[pB4.x*4] + SP[pB4.x*4+1] + SP[pB4.x*4+2] + SP[pB4.x*4+3]) : -1e30f;
                    float s1 = v1 ? (SP[pB4.y*4] + SP[pB4.y*4+1] + SP[pB4.y*4+2] + SP[pB4.y*4+3]) : -1e30f;
                    float s2 = v2 ? (SP[pB4.z*4] + SP[pB4.z*4+1] + SP[pB4.z*4+2] + SP[pB4.z*4+3]) : -1e30f;
                    float s3 = v3 ? (SP[pB4.w*4] + SP[pB4.w*4+1] + SP[pB4.w*4+2] + SP[pB4.w*4+3]) : -1e30f;
                    float m = fmaxf(fmaxf(s0, s1), fmaxf(s2, s3));
                    float e0 = v0 ? __expf(s0 - m) : 0.f;
                    float e1 = v1 ? __expf(s1 - m) : 0.f;
                    float e2 = v2 ? __expf(s2 - m) : 0.f;
                    float e3 = v3 ? __expf(s3 - m) : 0.f;
                    float inv = 1.f / (e0 + e1 + e2 + e3);
                    if (tid < DF) {
                        int q0 = max(pB4.x, 0), q1 = max(pB4.y, 0), q2 = max(pB4.z, 0), q3 = max(pB4.w, 0);
                        float agg = e0 * RB[q0 * 64 + tid];
                        agg = fmaf(e1, RB[q1 * 64 + tid], agg);
                        agg = fmaf(e2, RB[q2 * 64 + tid], agg);
                        agg = fmaf(e3, RB[q3 * 64 + tid], agg);
                        RB[OFF_XS + tid] = agg * inv;
                    }
                }
            }
            __syncthreads();   // xs ready (both DAGs)

            // ================== PHASE B: merge matvec + score partials ==================
            #pragma unroll
            for (int r = 0; r < 2; r++) {
                float* R = r ? RB : RA;
                const bool anyR = r ? anyB : anyA;
                float val;
                if (anyR) {
                    const ulonglong2* xb = (h == 0) ? (const ulonglong2*)(R + OFF_XS)
                                                    : (const ulonglong2*)(R + OFF_ATOMS + t * 64);
                    ull a0 = 0ull, a1 = 0ull, a2 = 0ull, a3 = 0ull;
                    #pragma unroll
                    for (int i = 0; i < 8; i++) {
                        ulonglong2 x0 = xb[2 * i];
                        ulonglong2 x1 = xb[2 * i + 1];
                        a0 = ffma2(W2[4 * i],     x0.x, a0);
                        a1 = ffma2(W2[4 * i + 1], x0.y, a1);
                        a2 = ffma2(W2[4 * i + 2], x1.x, a2);
                        a3 = ffma2(W2[4 * i + 3], x1.y, a3);
                    }
                    float sum = (lo2(a0) + hi2(a0)) + (lo2(a1) + hi2(a1))
                              + (lo2(a2) + hi2(a2)) + (lo2(a3) + hi2(a3));
                    sum += __shfl_xor_sync(0xffffffffu, sum, 1);
                    val = fmaxf(sum + bm, 0.f);
                } else {
                    // rare (~0.16%): no predecessors -> single path
                    float acc = 0.f;
                    if (g < DF) {
                        const float* wrow = Ws + g * DF + 31 * h;
                        const float* xr   = R + OFF_ATOMS + t * 64 + 31 * h;
                        #pragma unroll
                        for (int f = 0; f < 31; f++) acc = fmaf(__ldg(wrow + f), xr[f], acc);
                    }
                    float sum = acc + __shfl_xor_sync(0xffffffffu, acc, 1);
                    val = fmaxf(sum + bsg, 0.f);
                }
                if (h == 0 && g < DF) R[t * 64 + g] = val;
                float c = (h == 0) ? val * attw_g : 0.f;
                c = warp_sum(c);
                if (lane == 0) R[OFF_SCOREP + t * 4 + warp] = c;
            }
            __syncthreads();   // outs[t] + scoreP[t] ready
        }

        // ---- finalize both DAGs: sink output + pooling score ----
        if (h == 0 && g < DF) {
            g_last[(size_t)dA * 64 + g] = RA[47 * 64 + g];
            g_last[(size_t)dB * 64 + g] = RB[47 * 64 + g];
        }
        if (warp < 2) {
            const float* o = (warp == 0 ? RA : RB) + 47 * 64;
            float v = o[lane] * dagw_lo;
            v = fmaf(o[lane + 32], dagw_hi, v);
            v = warp_sum(v);
            if (lane == 0) g_score[warp == 0 ? dA : dB] = v;
        }
        __syncthreads();
    }
}

// =================================================================
// K2: per-block partial softmax pooling over 64 DAGs (deterministic)
// =================================================================
__global__ void k_pool_partial() {
    __shared__ float sm_e[64];
    __shared__ float sm_red[4];
    int tid = threadIdx.x;        // 128
    int b = blockIdx.x;
    int d0 = b * 64;

    float s = (tid < 64) ? g_score[d0 + tid] : -1e30f;
    float v = s;
    #pragma unroll
    for (int o = 16; o > 0; o >>= 1) v = fmaxf(v, __shfl_xor_sync(0xffffffffu, v, o));
    if ((tid & 31) == 0 && tid < 64) sm_red[tid >> 5] = v;
    __syncthreads();
    float m = fmaxf(sm_red[0], sm_red[1]);

    float e = (tid < 64) ? __expf(s - m) : 0.f;
    if (tid < 64) sm_e[tid] = e;
    float se = warp_sum(e);
    if ((tid & 31) == 0 && tid < 64) sm_red[2 + (tid >> 5)] = se;
    __syncthreads();
    if (tid == 0) { g_partS[b] = sm_red[2] + sm_red[3]; g_partM[b] = m; }
    if (tid < DF) {
        float acc = 0.f;
        #pragma unroll 8
        for (int dd = 0; dd < 64; dd++)
            acc = fmaf(sm_e[dd], g_last[(size_t)(d0 + dd) * 64 + tid], acc);
        g_partP[b * 64 + tid] = acc;
    }
}

// =================================================================
// K3: combine partials -> pooled -> sigmoid(W_final @ pooled + b)
// =================================================================
__global__ void k_final(const float* __restrict__ Wf, const float* __restrict__ bf,
                        float* __restrict__ out) {
    __shared__ float sw[K2B];
    __shared__ float smMax[16];
    __shared__ float smSum[16];
    __shared__ float smScalar[2];
    __shared__ float part8[8][64];
    __shared__ float pooled[64];
    int tid = threadIdx.x;        // 512
    int lane = tid & 31, warp = tid >> 5;

    float m = (tid < K2B) ? g_partM[tid] : -1e30f;
    float v = m;
    #pragma unroll
    for (int o = 16; o > 0; o >>= 1) v = fmaxf(v, __shfl_xor_sync(0xffffffffu, v, o));
    if (lane == 0) smMax[warp] = v;
    __syncthreads();
    if (tid == 0) {
        float M = smMax[0];
        #pragma unroll
        for (int w = 1; w < 16; w++) M = fmaxf(M, smMax[w]);
        smScalar[0] = M;
    }
    __syncthreads();
    float M = smScalar[0];

    float wb = (tid < K2B) ? __expf(m - M) : 0.f;
    if (tid < K2B) sw[tid] = wb;
    float ss = (tid < K2B) ? g_partS[tid] * wb : 0.f;
    ss = warp_sum(ss);
    if (lane == 0) smSum[warp] = ss;
    __syncthreads();
    if (tid == 0) {
        float S = 0.f;
        #pragma unroll
        for (int w = 0; w < 16; w++) S += smSum[w];
        smScalar[1] = 1.f / S;
    }
    __syncthreads();
    float invS = smScalar[1];

    // split-k pooled: 8 groups of 64 threads, each sums 32 partial blocks
    {
        int grp = tid >> 6, gg = tid & 63;
        float acc = 0.f;
        int b0 = grp * 32;
        #pragma unroll 8
        for (int b2 = b0; b2 < b0 + 32; b2++)
            acc = fmaf(sw[b2], g_partP[b2 * 64 + gg], acc);
        part8[grp][gg] = acc;
    }
    __syncthreads();
    if (tid < DF) {
        float acc = 0.f;
        #pragma unroll
        for (int c = 0; c < 8; c++) acc += part8[c][tid];
        pooled[tid] = acc * invS;
    }
    if (tid >= DF && tid < 64) pooled[tid] = 0.f;
    __syncthreads();

    for (int o = tid; o < NCLS; o += 512) {
        float acc = bf[o];
        #pragma unroll
        for (int gg = 0; gg < DF; gg++) acc = fmaf(Wf[o * DF + gg], pooled[gg], acc);
        out[o] = 1.f / (1.f + __expf(-acc));
    }
}

// =================================================================
extern "C" void kernel_launch(void* const* d_in, const int* in_sizes, int n_in,
                              void* d_out, int out_size) {
    const float* atoms = (const float*)d_in[0];
    const int*   preds = (const int*)  d_in[1];
    const float* Ws    = (const float*)d_in[2];
    const float* bs    = (const float*)d_in[3];
    const float* Wm    = (const float*)d_in[4];
    const float* bm    = (const float*)d_in[5];
    const float* attw  = (const float*)d_in[6];
    const float* dagw  = (const float*)d_in[7];
    const float* Wf    = (const float*)d_in[8];
    const float* bf    = (const float*)d_in[9];
    float* out = (float*)d_out;

    const int SMEM_BYTES = 2 * DAG_STRIDE * 4 + 128;   // 53120 + pad
    cudaFuncSetAttribute(k_dag, cudaFuncAttributeMaxDynamicSharedMemorySize, SMEM_BYTES);

    k_dag<<<608, 128, SMEM_BYTES>>>(atoms, preds, Wm, bm, attw, dagw, Ws, bs);
    k_pool_partial<<<K2B, 128>>>();
    k_final<<<1, 512>>>(Wf, bf, out);
}

// round 5
// speedup vs baseline: 1.2354x; 1.2354x over previous
#include <cuda_runtime.h>
#include <cstdint>

#define N_DAGS  16384
#define N_PAIRS (N_DAGS / 2)
#define NN      48
#define DF      62
#define NCLS    500
#define K2B     256

typedef unsigned long long ull;

// ---------------- scratch ----------------
__device__ float g_last [N_DAGS * 64];
__device__ float g_score[N_DAGS];
__device__ float g_partP[K2B * 64];
__device__ float g_partS[K2B];
__device__ float g_partM[K2B];

// ---------------- packed f32x2 helpers ----------------
__device__ __forceinline__ ull ffma2(ull a, ull b, ull c) {
    ull d;
    asm("fma.rn.f32x2 %0, %1, %2, %3;" : "=l"(d) : "l"(a), "l"(b), "l"(c));
    return d;
}
__device__ __forceinline__ ull pack2(float a, float b) {
    return (ull)__float_as_uint(a) | ((ull)__float_as_uint(b) << 32);
}
__device__ __forceinline__ float lo2(ull v) { return __uint_as_float((unsigned)v); }
__device__ __forceinline__ float hi2(ull v) { return __uint_as_float((unsigned)(v >> 32)); }

__device__ __forceinline__ float warp_sum(float v) {
    #pragma unroll
    for (int o = 16; o > 0; o >>= 1) v += __shfl_xor_sync(0xffffffffu, v, o);
    return v;
}
// 8-lane reduction: lanes {8k..8k+7} end with group sum
__device__ __forceinline__ float red8(float v) {
    v += __shfl_xor_sync(0xffffffffu, v, 4);
    v += __shfl_xor_sync(0xffffffffu, v, 2);
    v += __shfl_xor_sync(0xffffffffu, v, 1);
    return v;
}

// smem layout (floats)
#define O_OUTA   0          // 48*64
#define O_OUTB   3072       // 48*64
#define O_STAGE  6144       // 48*64 (atoms staging, one dag at a time)
#define O_XSA    9216       // 64
#define O_XSB    9280       // 64
#define O_SCA    9344       // 48*8
#define O_SCB    9728       // 48*8
#define O_PRDA   10112      // 48*4 ints
#define O_PRDB   10304      // 48*4 ints
#define SM_FLOATS 10496     // 41984 B

// =================================================================
// k_dag: 128 threads, 2 DAGs/block. Warps 0-1 -> dag A, 2-3 -> dag B.
// Thread output row g = tid&63 (full-k, W_xs in regs as f32x2 pairs).
// Atom-half contribution precomputed into outs[t][g] (barrier-free pass).
// =================================================================
__global__ void __launch_bounds__(128, 5)
k_dag(const float* __restrict__ atoms, const int* __restrict__ preds,
      const float* __restrict__ Wm,   const float* __restrict__ bmerge,
      const float* __restrict__ attw, const float* __restrict__ dagw,
      const float* __restrict__ Ws,   const float* __restrict__ bs) {
    __shared__ __align__(128) float SM[SM_FLOATS];

    const int tid  = threadIdx.x;
    const int lane = tid & 31;
    const int warp = tid >> 5;
    const int grp  = tid >> 6;       // my dag (step loop)
    const int g    = tid & 63;       // output row
    const int wo   = warp & 1;       // warp within dag group

    const bool act = (g < DF);
    const float attw_g = act ? attw[g] : 0.f;
    const float bm_g   = act ? bmerge[g] : 0.f;
    const float bs_g   = act ? bs[g] : 0.f;
    const float dagw_lo = dagw[lane];
    const float dagw_hi = (lane < DF - 32) ? dagw[lane + 32] : 0.f;

    for (int pr = blockIdx.x; pr < N_PAIRS; pr += gridDim.x) {
        const int dA = 2 * pr, dB = 2 * pr + 1;

        // ---- load preds for both dags ----
        {
            const int* PA = preds + (size_t)dA * NN * 4;
            const int* PB = preds + (size_t)dB * NN * 4;
            int* pa = (int*)(SM + O_PRDA);
            int* pb = (int*)(SM + O_PRDB);
            #pragma unroll
            for (int k = 0; k < 2; k++) {
                int idx = tid + k * 128;
                if (idx < NN * 4) { pa[idx] = PA[idx]; pb[idx] = PB[idx]; }
            }
            if (tid < 2) { SM[O_XSA + DF + tid] = 0.f; SM[O_XSB + DF + tid] = 0.f; }
        }

        // ============ per-dag: stage atoms, precompute atomP, singles ============
        #pragma unroll 1
        for (int r = 0; r < 2; r++) {
            const int d = r ? dB : dA;
            float* OUT = SM + (r ? O_OUTB : O_OUTA);
            float* SCP = SM + (r ? O_SCB : O_SCA);
            const int* prd = (const int*)(SM + (r ? O_PRDB : O_PRDA));
            __syncthreads();   // prev use of stage done / preds visible

            // stage atoms [48][64]
            const float* Ad = atoms + (size_t)d * NN * DF;
            #pragma unroll
            for (int k = 0; k < 24; k++) {
                int idx = tid + k * 128;
                int n = idx >> 6, c = idx & 63;
                SM[O_STAGE + idx] = (c < DF) ? Ad[n * DF + c] : 0.f;
            }
            __syncthreads();

            // precompute atomP -> OUT[t][g]  (t split: th = tid>>6)
            {
                ull Wa[32];
                #pragma unroll
                for (int j = 0; j < 32; j++) {
                    float w0 = 0.f, w1 = 0.f;
                    if (act && j < 31) {
                        w0 = Wm[g * 124 + DF + 2 * j];
                        w1 = Wm[g * 124 + DF + 2 * j + 1];
                    }
                    Wa[j] = pack2(w0, w1);
                }
                const int th = tid >> 6;
                #pragma unroll 2
                for (int t = th * 24; t < th * 24 + 24; t++) {
                    const ulonglong2* xb = (const ulonglong2*)(SM + O_STAGE + t * 64);
                    ull a0 = 0, a1 = 0, a2 = 0, a3 = 0;
                    #pragma unroll
                    for (int i = 0; i < 8; i++) {
                        ulonglong2 x0 = xb[2 * i];
                        ulonglong2 x1 = xb[2 * i + 1];
                        a0 = ffma2(Wa[4 * i],     x0.x, a0);
                        a1 = ffma2(Wa[4 * i + 1], x0.y, a1);
                        a2 = ffma2(Wa[4 * i + 2], x1.x, a2);
                        a3 = ffma2(Wa[4 * i + 3], x1.y, a3);
                    }
                    float s = (lo2(a0) + hi2(a0)) + (lo2(a1) + hi2(a1))
                            + (lo2(a2) + hi2(a2)) + (lo2(a3) + hi2(a3));
                    OUT[t * 64 + g] = act ? (s + bm_g) : 0.f;
                }
            }
            __syncthreads();

            // singles: pred-less nodes (t=0 always). Done by warps of this dag.
            if (warp >> 1 == r) {
                // build pred-less mask (uniform within warp)
                int4 q1 = *(const int4*)(prd + lane * 4);     // t = lane (<32<48)
                bool a1 = max(max(q1.x, q1.y), max(q1.z, q1.w)) >= 0;
                unsigned bl = __ballot_sync(0xffffffffu, a1);
                int t2 = 32 + lane;
                bool a2 = true;
                if (t2 < NN) {
                    int4 q2 = *(const int4*)(prd + t2 * 4);
                    a2 = max(max(q2.x, q2.y), max(q2.z, q2.w)) >= 0;
                }
                unsigned bh = __ballot_sync(0xffffffffu, a2);
                ull miss = (ull)(~bl) | ((ull)((~bh) & 0xffffu) << 32);
                while (miss) {
                    int t = __ffsll(miss) - 1;
                    miss &= miss - 1;
                    float acc = bs_g;
                    if (act) {
                        const float* wr = Ws + g * DF;
                        const float* xr = SM + O_STAGE + t * 64;
                        #pragma unroll 31
                        for (int f = 0; f < DF; f++)
                            acc = fmaf(__ldg(wr + f), xr[f], acc);
                    }
                    float val = fmaxf(acc, 0.f);
                    OUT[t * 64 + g] = act ? val : 0.f;
                    float c = act ? val * attw_g : 0.f;
                    c = red8(c);
                    if ((lane & 7) == 0) SCP[t * 8 + wo * 4 + (lane >> 3)] = c;
                }
            }
        }
        __syncthreads();

        // ---- load W_xs regs (atom-half regs now dead) ----
        ull W2[32];
        #pragma unroll
        for (int j = 0; j < 32; j++) {
            float w0 = 0.f, w1 = 0.f;
            if (act && j < 31) {
                w0 = Wm[g * 124 + 2 * j];
                w1 = Wm[g * 124 + 2 * j + 1];
            }
            W2[j] = pack2(w0, w1);
        }

        // ---- my-dag pointers + pred mask (per warp, own dag) ----
        float* OUT = SM + (grp ? O_OUTB : O_OUTA);
        float* XS  = SM + (grp ? O_XSB  : O_XSA);
        float* SCP = SM + (grp ? O_SCB  : O_SCA);
        const int* prd = (const int*)(SM + (grp ? O_PRDB : O_PRDA));
        unsigned bl, bh;
        {
            int4 q1 = *(const int4*)(prd + lane * 4);
            bool a1 = max(max(q1.x, q1.y), max(q1.z, q1.w)) >= 0;
            bl = __ballot_sync(0xffffffffu, a1);
            int t2 = 32 + lane;
            bool a2 = true;
            if (t2 < NN) {
                int4 q2 = *(const int4*)(prd + t2 * 4);
                a2 = max(max(q2.x, q2.y), max(q2.z, q2.w)) >= 0;
            }
            bh = __ballot_sync(0xffffffffu, a2);
        }

        // ================= step loop =================
        for (int t = 1; t < NN; t++) {
            const bool hasP = (t < 32) ? ((bl >> t) & 1u) : ((bh >> (t - 32)) & 1u);
            int4 p;
            if (hasP) {
                p = *(const int4*)(prd + t * 4);
                // scores: 2 LDS.128 per valid pred
                float s0 = -1e30f, s1 = -1e30f, s2 = -1e30f, s3 = -1e30f;
                if (p.x >= 0) { float4 u = *(const float4*)(SCP + p.x * 8);
                                float4 v = *(const float4*)(SCP + p.x * 8 + 4);
                                s0 = (u.x + u.y + u.z + u.w) + (v.x + v.y + v.z + v.w); }
                if (p.y >= 0) { float4 u = *(const float4*)(SCP + p.y * 8);
                                float4 v = *(const float4*)(SCP + p.y * 8 + 4);
                                s1 = (u.x + u.y + u.z + u.w) + (v.x + v.y + v.z + v.w); }
                if (p.z >= 0) { float4 u = *(const float4*)(SCP + p.z * 8);
                                float4 v = *(const float4*)(SCP + p.z * 8 + 4);
                                s2 = (u.x + u.y + u.z + u.w) + (v.x + v.y + v.z + v.w); }
                if (p.w >= 0) { float4 u = *(const float4*)(SCP + p.w * 8);
                                float4 v = *(const float4*)(SCP + p.w * 8 + 4);
                                s3 = (u.x + u.y + u.z + u.w) + (v.x + v.y + v.z + v.w); }
                float m = fmaxf(fmaxf(s0, s1), fmaxf(s2, s3));
                float e0 = (p.x >= 0) ? __expf(s0 - m) : 0.f;
                float e1 = (p.y >= 0) ? __expf(s1 - m) : 0.f;
                float e2 = (p.z >= 0) ? __expf(s2 - m) : 0.f;
                float e3 = (p.w >= 0) ? __expf(s3 - m) : 0.f;
                float inv = 1.f / (e0 + e1 + e2 + e3);
                if (act) {
                    int q0 = max(p.x, 0), q1 = max(p.y, 0), q2 = max(p.z, 0), q3 = max(p.w, 0);
                    float agg = e0 * OUT[q0 * 64 + g];
                    agg = fmaf(e1, OUT[q1 * 64 + g], agg);
                    agg = fmaf(e2, OUT[q2 * 64 + g], agg);
                    agg = fmaf(e3, OUT[q3 * 64 + g], agg);
                    XS[g] = agg * inv;
                }
            }
            __syncthreads();   // xs ready (both dags)

            if (hasP) {
                const ulonglong2* xb = (const ulonglong2*)XS;
                ull a0 = 0, a1 = 0, a2 = 0, a3 = 0;
                #pragma unroll
                for (int i = 0; i < 8; i++) {
                    ulonglong2 x0 = xb[2 * i];
                    ulonglong2 x1 = xb[2 * i + 1];
                    a0 = ffma2(W2[4 * i],     x0.x, a0);
                    a1 = ffma2(W2[4 * i + 1], x0.y, a1);
                    a2 = ffma2(W2[4 * i + 2], x1.x, a2);
                    a3 = ffma2(W2[4 * i + 3], x1.y, a3);
                }
                float s = (lo2(a0) + hi2(a0)) + (lo2(a1) + hi2(a1))
                        + (lo2(a2) + hi2(a2)) + (lo2(a3) + hi2(a3));
                float val = fmaxf(s + OUT[t * 64 + g], 0.f);   // atomP(+bias) preloaded
                if (act) OUT[t * 64 + g] = val;
                float c = act ? val * attw_g : 0.f;
                c = red8(c);
                if ((lane & 7) == 0) SCP[t * 8 + wo * 4 + (lane >> 3)] = c;
            }
            __syncthreads();   // outs[t]/scores[t] ready
        }

        // ---- finalize: sink vector + pooling score ----
        {
            const int d = grp ? dB : dA;
            if (act) g_last[(size_t)d * 64 + g] = OUT[47 * 64 + g];
            if (wo == 0) {
                float v = OUT[47 * 64 + lane] * dagw_lo;
                v = fmaf(OUT[47 * 64 + lane + 32], dagw_hi, v);
                v = warp_sum(v);
                if (lane == 0) g_score[d] = v;
            }
        }
    }
}

// =================================================================
// k_pool_partial: deterministic partial softmax pooling over 64 DAGs
// =================================================================
__global__ void k_pool_partial() {
    __shared__ float sm_e[64];
    __shared__ float sm_red[4];
    int tid = threadIdx.x;        // 128
    int b = blockIdx.x;
    int d0 = b * 64;

    float s = (tid < 64) ? g_score[d0 + tid] : -1e30f;
    float v = s;
    #pragma unroll
    for (int o = 16; o > 0; o >>= 1) v = fmaxf(v, __shfl_xor_sync(0xffffffffu, v, o));
    if ((tid & 31) == 0 && tid < 64) sm_red[tid >> 5] = v;
    __syncthreads();
    float m = fmaxf(sm_red[0], sm_red[1]);

    float e = (tid < 64) ? __expf(s - m) : 0.f;
    if (tid < 64) sm_e[tid] = e;
    float se = warp_sum(e);
    if ((tid & 31) == 0 && tid < 64) sm_red[2 + (tid >> 5)] = se;
    __syncthreads();
    if (tid == 0) { g_partS[b] = sm_red[2] + sm_red[3]; g_partM[b] = m; }
    if (tid < DF) {
        float acc = 0.f;
        #pragma unroll 8
        for (int dd = 0; dd < 64; dd++)
            acc = fmaf(sm_e[dd], g_last[(size_t)(d0 + dd) * 64 + tid], acc);
        g_partP[b * 64 + tid] = acc;
    }
}

// =================================================================
// k_final: combine partials -> pooled -> sigmoid(W_final @ pooled + b)
// =================================================================
__global__ void k_final(const float* __restrict__ Wf, const float* __restrict__ bf,
                        float* __restrict__ out) {
    __shared__ float sw[K2B];
    __shared__ float smMax[16];
    __shared__ float smSum[16];
    __shared__ float smScalar[2];
    __shared__ float part8[8][64];
    __shared__ float pooled[64];
    int tid = threadIdx.x;        // 512
    int lane = tid & 31, warp = tid >> 5;

    float m = (tid < K2B) ? g_partM[tid] : -1e30f;
    float v = m;
    #pragma unroll
    for (int o = 16; o > 0; o >>= 1) v = fmaxf(v, __shfl_xor_sync(0xffffffffu, v, o));
    if (lane == 0) smMax[warp] = v;
    __syncthreads();
    if (tid == 0) {
        float M = smMax[0];
        #pragma unroll
        for (int w = 1; w < 16; w++) M = fmaxf(M, smMax[w]);
        smScalar[0] = M;
    }
    __syncthreads();
    float M = smScalar[0];

    float wb = (tid < K2B) ? __expf(m - M) : 0.f;
    if (tid < K2B) sw[tid] = wb;
    float ss = (tid < K2B) ? g_partS[tid] * wb : 0.f;
    ss = warp_sum(ss);
    if (lane == 0) smSum[warp] = ss;
    __syncthreads();
    if (tid == 0) {
        float S = 0.f;
        #pragma unroll
        for (int w = 0; w < 16; w++) S += smSum[w];
        smScalar[1] = 1.f / S;
    }
    __syncthreads();
    float invS = smScalar[1];

    {
        int grp = tid >> 6, gg = tid & 63;
        float acc = 0.f;
        int b0 = grp * 32;
        #pragma unroll 8
        for (int b2 = b0; b2 < b0 + 32; b2++)
            acc = fmaf(sw[b2], g_partP[b2 * 64 + gg], acc);
        part8[grp][gg] = acc;
    }
    __syncthreads();
    if (tid < DF) {
        float acc = 0.f;
        #pragma unroll
        for (int c = 0; c < 8; c++) acc += part8[c][tid];
        pooled[tid] = acc * invS;
    }
    if (tid >= DF && tid < 64) pooled[tid] = 0.f;
    __syncthreads();

    for (int o = tid; o < NCLS; o += 512) {
        float acc = bf[o];
        #pragma unroll
        for (int gg = 0; gg < DF; gg++) acc = fmaf(Wf[o * DF + gg], pooled[gg], acc);
        out[o] = 1.f / (1.f + __expf(-acc));
    }
}

// =================================================================
extern "C" void kernel_launch(void* const* d_in, const int* in_sizes, int n_in,
                              void* d_out, int out_size) {
    const float* atoms = (const float*)d_in[0];
    const int*   preds = (const int*)  d_in[1];
    const float* Ws    = (const float*)d_in[2];
    const float* bs    = (const float*)d_in[3];
    const float* Wm    = (const float*)d_in[4];
    const float* bm    = (const float*)d_in[5];
    const float* attw  = (const float*)d_in[6];
    const float* dagw  = (const float*)d_in[7];
    const float* Wf    = (const float*)d_in[8];
    const float* bf    = (const float*)d_in[9];
    float* out = (float*)d_out;

    k_dag<<<740, 128>>>(atoms, preds, Wm, bm, attw, dagw, Ws, bs);
    k_pool_partial<<<K2B, 128>>>();
    k_final<<<1, 512>>>(Wf, bf, out);
}

// round 6
// speedup vs baseline: 1.8097x; 1.4650x over previous
#include <cuda_runtime.h>
#include <cstdint>

#define N_DAGS 16384
#define NN     48
#define DF     62
#define NCLS   500
#define K2B    256

typedef unsigned long long ull;

// ---------------- scratch (no cudaMalloc allowed) ----------------
__device__ float g_pre [(size_t)N_DAGS * NN * 64];   // per-node precomputed atom-half
__device__ float g_last[N_DAGS * 64];
__device__ float g_score[N_DAGS];
__device__ float g_partP[K2B * 64];
__device__ float g_partS[K2B];
__device__ float g_partM[K2B];

// ---------------- packed f32x2 helpers ----------------
__device__ __forceinline__ ull ffma2(ull a, ull b, ull c) {
    ull d;
    asm("fma.rn.f32x2 %0, %1, %2, %3;" : "=l"(d) : "l"(a), "l"(b), "l"(c));
    return d;
}
__device__ __forceinline__ ull pack2(float a, float b) {
    return (ull)__float_as_uint(a) | ((ull)__float_as_uint(b) << 32);
}
__device__ __forceinline__ float lo2(ull v) { return __uint_as_float((unsigned)v); }
__device__ __forceinline__ float hi2(ull v) { return __uint_as_float((unsigned)(v >> 32)); }

__device__ __forceinline__ float warp_sum(float v) {
    #pragma unroll
    for (int o = 16; o > 0; o >>= 1) v += __shfl_xor_sync(0xffffffffu, v, o);
    return v;
}
__device__ __forceinline__ float red8(float v) {
    v += __shfl_xor_sync(0xffffffffu, v, 4);
    v += __shfl_xor_sync(0xffffffffu, v, 2);
    v += __shfl_xor_sync(0xffffffffu, v, 1);
    return v;
}
__device__ __forceinline__ int max4(int4 q) {
    return max(max(q.x, q.y), max(q.z, q.w));
}

// =================================================================
// k_pre: per-node input-only half.
//   pred-ful : g_pre[n] = Wm_atom @ atom[n] + b_merge      (pre-activation)
//   pred-less: g_pre[n] = relu(Ws @ atom[n] + bs)          (final value)
// 1 warp per DAG chunk; thread owns output rows (2*lane, 2*lane+1).
// =================================================================
__global__ void __launch_bounds__(128, 3)
k_pre(const float* __restrict__ atoms, const int* __restrict__ preds,
      const float* __restrict__ Wm, const float* __restrict__ bmerge,
      const float* __restrict__ Ws, const float* __restrict__ bs) {
    extern __shared__ float PSM[];                 // 4 warps * 48*64 floats
    const int tid = threadIdx.x, lane = tid & 31, warp = tid >> 5;
    float* BUF = PSM + warp * (NN * 64);

    const int r0 = 2 * lane, r1 = 2 * lane + 1;
    const bool a0 = (r0 < DF), a1 = (r1 < DF);

    ull WA[32], WB[32];
    #pragma unroll
    for (int j = 0; j < 32; j++) {
        WA[j] = (a0 && j < 31) ? pack2(__ldg(&Wm[r0*124 + DF + 2*j]), __ldg(&Wm[r0*124 + DF + 2*j + 1])) : 0ull;
        WB[j] = (a1 && j < 31) ? pack2(__ldg(&Wm[r1*124 + DF + 2*j]), __ldg(&Wm[r1*124 + DF + 2*j + 1])) : 0ull;
    }
    const float bm0 = a0 ? bmerge[r0] : 0.f, bm1 = a1 ? bmerge[r1] : 0.f;
    const float bs0 = a0 ? bs[r0] : 0.f,     bs1 = a1 ? bs[r1] : 0.f;

    const int gw = blockIdx.x * 4 + warp, nw = gridDim.x * 4;
    for (int d = gw; d < N_DAGS; d += nw) {
        // predecessor masks
        const int4* P4 = (const int4*)(preds + (size_t)d * NN * 4);
        int4 q1 = __ldg(P4 + lane);
        unsigned bl = __ballot_sync(0xffffffffu, max4(q1) >= 0);
        bool h2 = true;
        if (lane < 16) { int4 q2 = __ldg(P4 + 32 + lane); h2 = (max4(q2) >= 0); }
        unsigned bh = __ballot_sync(0xffffffffu, h2);

        // stage atoms: 48 rows of 62 floats (= 31 ull), chunks of 12 rows
        const ull* A8 = (const ull*)(atoms + (size_t)d * NN * DF);
        #pragma unroll
        for (int c = 0; c < 4; c++) {
            ull v[12];
            #pragma unroll
            for (int r = 0; r < 12; r++)
                v[r] = (lane < 31) ? __ldg(A8 + (size_t)(c*12 + r) * 31 + lane) : 0ull;
            #pragma unroll
            for (int r = 0; r < 12; r++)
                *(ull*)&BUF[(c*12 + r) * 64 + 2*lane] = (lane < 31) ? v[r] : 0ull;  // lane31 zeros pads 62,63
        }
        __syncwarp();

        for (int t = 0; t < NN; t++) {
            const bool hasP = (t < 32) ? ((bl >> t) & 1u) : ((bh >> (t - 32)) & 1u);
            float o0, o1;
            if (hasP) {
                const ulonglong2* xb = (const ulonglong2*)&BUF[t * 64];
                ull A0=0,A1=0,A2=0,A3=0,B0=0,B1=0,B2=0,B3=0;
                #pragma unroll
                for (int i = 0; i < 8; i++) {
                    ulonglong2 u = xb[2*i], w = xb[2*i + 1];
                    A0 = ffma2(WA[4*i],   u.x, A0); A1 = ffma2(WA[4*i+1], u.y, A1);
                    A2 = ffma2(WA[4*i+2], w.x, A2); A3 = ffma2(WA[4*i+3], w.y, A3);
                    B0 = ffma2(WB[4*i],   u.x, B0); B1 = ffma2(WB[4*i+1], u.y, B1);
                    B2 = ffma2(WB[4*i+2], w.x, B2); B3 = ffma2(WB[4*i+3], w.y, B3);
                }
                o0 = (lo2(A0)+hi2(A0)) + (lo2(A1)+hi2(A1)) + (lo2(A2)+hi2(A2)) + (lo2(A3)+hi2(A3)) + bm0;
                o1 = (lo2(B0)+hi2(B0)) + (lo2(B1)+hi2(B1)) + (lo2(B2)+hi2(B2)) + (lo2(B3)+hi2(B3)) + bm1;
            } else {
                // rare: pred-less -> full single path (final, relu'd)
                float acc0 = bs0, acc1 = bs1;
                const float* xr = &BUF[t * 64];
                for (int f = 0; f < DF; f++) {
                    float x = xr[f];
                    if (a0) acc0 = fmaf(__ldg(&Ws[r0*DF + f]), x, acc0);
                    if (a1) acc1 = fmaf(__ldg(&Ws[r1*DF + f]), x, acc1);
                }
                o0 = fmaxf(acc0, 0.f); o1 = fmaxf(acc1, 0.f);
            }
            float2 o = make_float2(a0 ? o0 : 0.f, a1 ? o1 : 0.f);
            *(float2*)&g_pre[((size_t)d * NN + t) * 64 + 2*lane] = o;
        }
        __syncwarp();
    }
}

// =================================================================
// k_dag: recurrent step loop. ONE WARP PER DAG, no __syncthreads.
// Thread owns output rows (2*lane, 2*lane+1); merge-x weights in regs.
// Per-warp smem region: OUT[48*64] | XS[64] | SCB[48*4] | PRD[48*4 int]
// =================================================================
#define RW_FLOATS 3520   // 3072 + 64 + 192 + 192

__global__ void __launch_bounds__(128, 3)
k_dag(const int* __restrict__ preds, const float* __restrict__ attw,
      const float* __restrict__ dagw, const float* __restrict__ Wm) {
    extern __shared__ float DSM[];
    const int tid = threadIdx.x, lane = tid & 31, warp = tid >> 5;
    float* R   = DSM + warp * RW_FLOATS;
    float* OUT = R;
    float* XS  = R + 3072;
    float* SCB = R + 3136;
    int*   PRD = (int*)(R + 3328);

    const int r0 = 2 * lane, r1 = 2 * lane + 1;
    const bool a0 = (r0 < DF), a1 = (r1 < DF);

    ull WA[32], WB[32];
    #pragma unroll
    for (int j = 0; j < 32; j++) {
        WA[j] = (a0 && j < 31) ? pack2(__ldg(&Wm[r0*124 + 2*j]), __ldg(&Wm[r0*124 + 2*j + 1])) : 0ull;
        WB[j] = (a1 && j < 31) ? pack2(__ldg(&Wm[r1*124 + 2*j]), __ldg(&Wm[r1*124 + 2*j + 1])) : 0ull;
    }
    const float aw0 = a0 ? attw[r0] : 0.f, aw1 = a1 ? attw[r1] : 0.f;
    const float dg0 = a0 ? dagw[r0] : 0.f, dg1 = a1 ? dagw[r1] : 0.f;

    const int gw = blockIdx.x * 4 + warp, nw = gridDim.x * 4;
    for (int d = gw; d < N_DAGS; d += nw) {
        // preds + masks
        const int4* P4 = (const int4*)(preds + (size_t)d * NN * 4);
        int4 q1 = __ldg(P4 + lane);
        ((int4*)PRD)[lane] = q1;
        unsigned bl = __ballot_sync(0xffffffffu, max4(q1) >= 0);
        bool h2 = true;
        if (lane < 16) { int4 q2 = __ldg(P4 + 32 + lane); ((int4*)PRD)[32 + lane] = q2; h2 = (max4(q2) >= 0); }
        unsigned bh = __ballot_sync(0xffffffffu, h2);

        // load precomputed tile (3072 floats)
        const float4* src = (const float4*)(g_pre + (size_t)d * (NN * 64));
        #pragma unroll
        for (int k = 0; k < 24; k++)
            ((float4*)OUT)[lane + 32*k] = __ldg(src + lane + 32*k);
        __syncwarp();

        // scores for pred-less nodes (incl t=0): they are final values already
        ull miss = (ull)(~bl) | ((ull)((~bh) & 0xffffu) << 32);
        while (miss) {
            int t = __ffsll(miss) - 1;
            miss &= miss - 1;
            float2 o = *(float2*)&OUT[t*64 + r0];
            float c = o.x * aw0 + o.y * aw1;
            c = warp_sum(c);
            if (lane < 4) SCB[t*4 + lane] = (lane == 0) ? c : 0.f;
        }
        __syncwarp();

        // ================= recurrent step loop =================
        for (int t = 1; t < NN; t++) {
            const bool hasP = (t < 32) ? ((bl >> t) & 1u) : ((bh >> (t - 32)) & 1u);
            if (!hasP) continue;     // warp-uniform

            int4 p = ((int4*)PRD)[t];
            int q0 = max(p.x, 0), qq1 = max(p.y, 0), q2 = max(p.z, 0), q3 = max(p.w, 0);
            float4 c0 = *(float4*)&SCB[q0*4];
            float4 c1 = *(float4*)&SCB[qq1*4];
            float4 c2 = *(float4*)&SCB[q2*4];
            float4 c3 = *(float4*)&SCB[q3*4];
            float s0 = (p.x >= 0) ? (c0.x + c0.y + c0.z + c0.w) : -1e30f;
            float s1 = (p.y >= 0) ? (c1.x + c1.y + c1.z + c1.w) : -1e30f;
            float s2 = (p.z >= 0) ? (c2.x + c2.y + c2.z + c2.w) : -1e30f;
            float s3 = (p.w >= 0) ? (c3.x + c3.y + c3.z + c3.w) : -1e30f;
            float m = fmaxf(fmaxf(s0, s1), fmaxf(s2, s3));
            float e0 = (p.x >= 0) ? __expf(s0 - m) : 0.f;
            float e1 = (p.y >= 0) ? __expf(s1 - m) : 0.f;
            float e2 = (p.z >= 0) ? __expf(s2 - m) : 0.f;
            float e3 = (p.w >= 0) ? __expf(s3 - m) : 0.f;
            float inv = 1.f / (e0 + e1 + e2 + e3);

            float2 u0 = *(float2*)&OUT[q0*64 + r0];
            float2 u1 = *(float2*)&OUT[qq1*64 + r0];
            float2 u2 = *(float2*)&OUT[q2*64 + r0];
            float2 u3 = *(float2*)&OUT[q3*64 + r0];
            float x0 = (e0*u0.x + e1*u1.x + e2*u2.x + e3*u3.x) * inv;
            float x1 = (e0*u0.y + e1*u1.y + e2*u2.y + e3*u3.y) * inv;
            *(float2*)&XS[r0] = make_float2(x0, x1);   // lane31 writes zeros (rows 62,63)
            __syncwarp();

            const ulonglong2* xb = (const ulonglong2*)XS;
            ull A0=0,A1=0,A2=0,A3=0,B0=0,B1=0,B2=0,B3=0;
            #pragma unroll
            for (int i = 0; i < 8; i++) {
                ulonglong2 u = xb[2*i], w = xb[2*i + 1];
                A0 = ffma2(WA[4*i],   u.x, A0); A1 = ffma2(WA[4*i+1], u.y, A1);
                A2 = ffma2(WA[4*i+2], w.x, A2); A3 = ffma2(WA[4*i+3], w.y, A3);
                B0 = ffma2(WB[4*i],   u.x, B0); B1 = ffma2(WB[4*i+1], u.y, B1);
                B2 = ffma2(WB[4*i+2], w.x, B2); B3 = ffma2(WB[4*i+3], w.y, B3);
            }
            float sA = (lo2(A0)+hi2(A0)) + (lo2(A1)+hi2(A1)) + (lo2(A2)+hi2(A2)) + (lo2(A3)+hi2(A3));
            float sB = (lo2(B0)+hi2(B0)) + (lo2(B1)+hi2(B1)) + (lo2(B2)+hi2(B2)) + (lo2(B3)+hi2(B3));
            float2 ap = *(float2*)&OUT[t*64 + r0];     // atom-half + bias (precomputed)
            float v0 = fmaxf(sA + ap.x, 0.f);
            float v1 = fmaxf(sB + ap.y, 0.f);
            *(float2*)&OUT[t*64 + r0] = make_float2(a0 ? v0 : 0.f, a1 ? v1 : 0.f);

            float c = v0 * aw0 + v1 * aw1;
            c = red8(c);                               // 4 partials (8-lane groups)
            if ((lane & 7) == 0) SCB[t*4 + (lane >> 3)] = c;
            __syncwarp();
        }

        // finalize DAG
        float2 last = *(float2*)&OUT[47*64 + r0];
        *(float2*)&g_last[(size_t)d*64 + r0] = last;
        float v = last.x * dg0 + last.y * dg1;
        v = warp_sum(v);
        if (lane == 0) g_score[d] = v;
        __syncwarp();
    }
}

// =================================================================
// k_pool_partial: deterministic partial softmax pooling over 64 DAGs
// =================================================================
__global__ void k_pool_partial() {
    __shared__ float sm_e[64];
    __shared__ float sm_red[4];
    int tid = threadIdx.x;        // 128
    int b = blockIdx.x;
    int d0 = b * 64;

    float s = (tid < 64) ? g_score[d0 + tid] : -1e30f;
    float v = s;
    #pragma unroll
    for (int o = 16; o > 0; o >>= 1) v = fmaxf(v, __shfl_xor_sync(0xffffffffu, v, o));
    if ((tid & 31) == 0 && tid < 64) sm_red[tid >> 5] = v;
    __syncthreads();
    float m = fmaxf(sm_red[0], sm_red[1]);

    float e = (tid < 64) ? __expf(s - m) : 0.f;
    if (tid < 64) sm_e[tid] = e;
    float se = warp_sum(e);
    if ((tid & 31) == 0 && tid < 64) sm_red[2 + (tid >> 5)] = se;
    __syncthreads();
    if (tid == 0) { g_partS[b] = sm_red[2] + sm_red[3]; g_partM[b] = m; }
    if (tid < DF) {
        float acc = 0.f;
        #pragma unroll 8
        for (int dd = 0; dd < 64; dd++)
            acc = fmaf(sm_e[dd], g_last[(size_t)(d0 + dd) * 64 + tid], acc);
        g_partP[b * 64 + tid] = acc;
    }
}

// =================================================================
// k_final: combine partials -> pooled -> sigmoid(W_final @ pooled + b)
// =================================================================
__global__ void k_final(const float* __restrict__ Wf, const float* __restrict__ bf,
                        float* __restrict__ out) {
    __shared__ float sw[K2B];
    __shared__ float smMax[16];
    __shared__ float smSum[16];
    __shared__ float smScalar[2];
    __shared__ float part8[8][64];
    __shared__ float pooled[64];
    int tid = threadIdx.x;        // 512
    int lane = tid & 31, warp = tid >> 5;

    float m = (tid < K2B) ? g_partM[tid] : -1e30f;
    float v = m;
    #pragma unroll
    for (int o = 16; o > 0; o >>= 1) v = fmaxf(v, __shfl_xor_sync(0xffffffffu, v, o));
    if (lane == 0) smMax[warp] = v;
    __syncthreads();
    if (tid == 0) {
        float M = smMax[0];
        #pragma unroll
        for (int w = 1; w < 16; w++) M = fmaxf(M, smMax[w]);
        smScalar[0] = M;
    }
    __syncthreads();
    float M = smScalar[0];

    float wb = (tid < K2B) ? __expf(m - M) : 0.f;
    if (tid < K2B) sw[tid] = wb;
    float ss = (tid < K2B) ? g_partS[tid] * wb : 0.f;
    ss = warp_sum(ss);
    if (lane == 0) smSum[warp] = ss;
    __syncthreads();
    if (tid == 0) {
        float S = 0.f;
        #pragma unroll
        for (int w = 0; w < 16; w++) S += smSum[w];
        smScalar[1] = 1.f / S;
    }
    __syncthreads();
    float invS = smScalar[1];

    {
        int grp = tid >> 6, gg = tid & 63;
        float acc = 0.f;
        int b0 = grp * 32;
        #pragma unroll 8
        for (int b2 = b0; b2 < b0 + 32; b2++)
            acc = fmaf(sw[b2], g_partP[b2 * 64 + gg], acc);
        part8[grp][gg] = acc;
    }
    __syncthreads();
    if (tid < DF) {
        float acc = 0.f;
        #pragma unroll
        for (int c = 0; c < 8; c++) acc += part8[c][tid];
        pooled[tid] = acc * invS;
    }
    if (tid >= DF && tid < 64) pooled[tid] = 0.f;
    __syncthreads();

    for (int o = tid; o < NCLS; o += 512) {
        float acc = bf[o];
        #pragma unroll
        for (int gg = 0; gg < DF; gg++) acc = fmaf(Wf[o * DF + gg], pooled[gg], acc);
        out[o] = 1.f / (1.f + __expf(-acc));
    }
}

// =================================================================
extern "C" void kernel_launch(void* const* d_in, const int* in_sizes, int n_in,
                              void* d_out, int out_size) {
    const float* atoms = (const float*)d_in[0];
    const int*   preds = (const int*)  d_in[1];
    const float* Ws    = (const float*)d_in[2];
    const float* bs    = (const float*)d_in[3];
    const float* Wm    = (const float*)d_in[4];
    const float* bm    = (const float*)d_in[5];
    const float* attw  = (const float*)d_in[6];
    const float* dagw  = (const float*)d_in[7];
    const float* Wf    = (const float*)d_in[8];
    const float* bf    = (const float*)d_in[9];
    float* out = (float*)d_out;

    const int PSM_BYTES = 4 * NN * 64 * 4;          // 49152
    const int DSM_BYTES = 4 * RW_FLOATS * 4;        // 56320
    cudaFuncSetAttribute(k_pre, cudaFuncAttributeMaxDynamicSharedMemorySize, PSM_BYTES);
    cudaFuncSetAttribute(k_dag, cudaFuncAttributeMaxDynamicSharedMemorySize, DSM_BYTES);

    k_pre<<<444, 128, PSM_BYTES>>>(atoms, preds, Wm, bm, Ws, bs);
    k_dag<<<444, 128, DSM_BYTES>>>(preds, attw, dagw, Wm);
    k_pool_partial<<<K2B, 128>>>();
    k_final<<<1, 512>>>(Wf, bf, out);
}

// round 8
// speedup vs baseline: 1.8942x; 1.0467x over previous
#include <cuda_runtime.h>
#include <cstdint>

#define N_DAGS 16384
#define NPAIR  (N_DAGS / 2)
#define NN     48
#define DF     62
#define NCLS   500
#define K2B    256

typedef unsigned long long ull;

// ---------------- scratch ----------------
__device__ float g_last [N_DAGS * 64];
__device__ float g_score[N_DAGS];
__device__ float g_partP[K2B * 64];
__device__ float g_partS[K2B];
__device__ float g_partM[K2B];

// ---------------- packed f32x2 helpers ----------------
__device__ __forceinline__ ull ffma2(ull a, ull b, ull c) {
    ull d;
    asm("fma.rn.f32x2 %0, %1, %2, %3;" : "=l"(d) : "l"(a), "l"(b), "l"(c));
    return d;
}
__device__ __forceinline__ ull pack2(float a, float b) {
    return (ull)__float_as_uint(a) | ((ull)__float_as_uint(b) << 32);
}
__device__ __forceinline__ float lo2(ull v) { return __uint_as_float((unsigned)v); }
__device__ __forceinline__ float hi2(ull v) { return __uint_as_float((unsigned)(v >> 32)); }

__device__ __forceinline__ float warp_sum(float v) {
    #pragma unroll
    for (int o = 16; o > 0; o >>= 1) v += __shfl_xor_sync(0xffffffffu, v, o);
    return v;
}
__device__ __forceinline__ float red8(float v) {
    v += __shfl_xor_sync(0xffffffffu, v, 4);
    v += __shfl_xor_sync(0xffffffffu, v, 2);
    v += __shfl_xor_sync(0xffffffffu, v, 1);
    return v;
}
__device__ __forceinline__ int max4(int4 q) { return max(max(q.x, q.y), max(q.z, q.w)); }
__device__ __forceinline__ bool mbit(unsigned bl, unsigned bh, int t) {
    return (t < 32) ? ((bl >> t) & 1u) : ((bh >> (t - 32)) & 1u);
}

// per-warp smem region: 7040 floats (28160 B)
#define RWF    7040
#define W_OUT0 0
#define W_OUT1 3072
#define W_XS0  6144
#define W_XS1  6208
#define W_SCB0 6272
#define W_SCB1 6464
#define W_PRD0 6656
#define W_PRD1 6848
#define DSM_BYTES (4 * RWF * 4)   // 112640

// =================================================================
// k_dag: fused precompute + recurrent loop. ONE WARP = TWO DAGs.
// Thread owns rows (2*lane, 2*lane+1) of both DAGs; weights in regs
// (shared across the two DAG streams).
// =================================================================
__global__ void __launch_bounds__(128, 2)
k_dag(const float* __restrict__ atoms, const int* __restrict__ preds,
      const float* __restrict__ Wm,   const float* __restrict__ bmerge,
      const float* __restrict__ Ws,   const float* __restrict__ bs,
      const float* __restrict__ attw, const float* __restrict__ dagw) {
    extern __shared__ float DSM[];
    const int tid = threadIdx.x, lane = tid & 31, warp = tid >> 5;
    float* R    = DSM + warp * RWF;
    float* OUT0 = R + W_OUT0;
    float* OUT1 = R + W_OUT1;
    float* XS0  = R + W_XS0;
    float* XS1  = R + W_XS1;
    float* SCB0 = R + W_SCB0;
    float* SCB1 = R + W_SCB1;
    int*   PRD0 = (int*)(R + W_PRD0);
    int*   PRD1 = (int*)(R + W_PRD1);

    const int r0 = 2 * lane, r1 = 2 * lane + 1;
    const bool a0 = (r0 < DF), a1 = (r1 < DF);
    const float aw0 = a0 ? attw[r0] : 0.f, aw1 = a1 ? attw[r1] : 0.f;
    const float dg0 = a0 ? dagw[r0] : 0.f, dg1 = a1 ? dagw[r1] : 0.f;
    const float bm0 = a0 ? bmerge[r0] : 0.f, bm1 = a1 ? bmerge[r1] : 0.f;
    const float bs0 = a0 ? bs[r0] : 0.f,     bs1 = a1 ? bs[r1] : 0.f;

    ull W[64];   // reloaded per phase (atom-half, then x-half)

    const int gw = blockIdx.x * 4 + warp, nw = gridDim.x * 4;
    for (int pr = gw; pr < NPAIR; pr += nw) {
        const int d0 = 2 * pr, d1 = 2 * pr + 1;

        // ---- preds + masks ----
        unsigned bl0, bh0, bl1, bh1;
        {
            const int4* P0 = (const int4*)(preds + (size_t)d0 * NN * 4);
            const int4* P1 = (const int4*)(preds + (size_t)d1 * NN * 4);
            int4 q = __ldg(P0 + lane); ((int4*)PRD0)[lane] = q;
            bl0 = __ballot_sync(0xffffffffu, max4(q) >= 0);
            bool h = true;
            if (lane < 16) { int4 q2 = __ldg(P0 + 32 + lane); ((int4*)PRD0)[32 + lane] = q2; h = max4(q2) >= 0; }
            bh0 = __ballot_sync(0xffffffffu, h);
            q = __ldg(P1 + lane); ((int4*)PRD1)[lane] = q;
            bl1 = __ballot_sync(0xffffffffu, max4(q) >= 0);
            h = true;
            if (lane < 16) { int4 q2 = __ldg(P1 + 32 + lane); ((int4*)PRD1)[32 + lane] = q2; h = max4(q2) >= 0; }
            bh1 = __ballot_sync(0xffffffffu, h);
        }

        // ---- stage atoms into OUT rows (zero-padded cols 62,63) ----
        #pragma unroll 1
        for (int e = 0; e < 2; e++) {
            float* O = e ? OUT1 : OUT0;
            const ull* A8 = (const ull*)(atoms + (size_t)(e ? d1 : d0) * NN * DF);
            #pragma unroll
            for (int c = 0; c < 4; c++) {
                ull v[12];
                #pragma unroll
                for (int r = 0; r < 12; r++)
                    v[r] = (lane < 31) ? __ldg(A8 + (size_t)(c * 12 + r) * 31 + lane) : 0ull;
                #pragma unroll
                for (int r = 0; r < 12; r++)
                    *(ull*)&O[(c * 12 + r) * 64 + 2 * lane] = (lane < 31) ? v[r] : 0ull;
            }
        }
        __syncwarp();

        // ---- load atom-half merge weights ----
        #pragma unroll
        for (int j = 0; j < 32; j++) {
            W[j]      = (a0 && j < 31) ? pack2(__ldg(&Wm[r0*124 + DF + 2*j]), __ldg(&Wm[r0*124 + DF + 2*j + 1])) : 0ull;
            W[32 + j] = (a1 && j < 31) ? pack2(__ldg(&Wm[r1*124 + DF + 2*j]), __ldg(&Wm[r1*124 + DF + 2*j + 1])) : 0ull;
        }

        // ---- atomP in place, groups of 4 rows, both dags ----
        #pragma unroll 1
        for (int grp = 0; grp < 12; grp++) {
            float2 res[2][4];
            #pragma unroll
            for (int e = 0; e < 2; e++) {
                float* O = e ? OUT1 : OUT0;
                const unsigned mbl = e ? bl1 : bl0, mbh = e ? bh1 : bh0;
                #pragma unroll
                for (int k = 0; k < 4; k++) {
                    const int t = grp * 4 + k;
                    float o0, o1;
                    if (mbit(mbl, mbh, t)) {
                        const ulonglong2* xb = (const ulonglong2*)&O[t * 64];
                        ull A0=0,A1=0,A2=0,A3=0,B0=0,B1=0,B2=0,B3=0;
                        #pragma unroll
                        for (int i = 0; i < 8; i++) {
                            ulonglong2 u = xb[2*i], w = xb[2*i + 1];
                            A0 = ffma2(W[4*i],      u.x, A0); A1 = ffma2(W[4*i+1],    u.y, A1);
                            A2 = ffma2(W[4*i+2],    w.x, A2); A3 = ffma2(W[4*i+3],    w.y, A3);
                            B0 = ffma2(W[32+4*i],   u.x, B0); B1 = ffma2(W[32+4*i+1], u.y, B1);
                            B2 = ffma2(W[32+4*i+2], w.x, B2); B3 = ffma2(W[32+4*i+3], w.y, B3);
                        }
                        o0 = (lo2(A0)+hi2(A0)) + (lo2(A1)+hi2(A1)) + (lo2(A2)+hi2(A2)) + (lo2(A3)+hi2(A3)) + bm0;
                        o1 = (lo2(B0)+hi2(B0)) + (lo2(B1)+hi2(B1)) + (lo2(B2)+hi2(B2)) + (lo2(B3)+hi2(B3)) + bm1;
                    } else {
                        // pred-less (t=0 + rare): full single path, final value
                        float acc0 = bs0, acc1 = bs1;
                        const float* xr = &O[t * 64];
                        #pragma unroll 31
                        for (int f = 0; f < DF; f++) {
                            float x = xr[f];
                            if (a0) acc0 = fmaf(__ldg(&Ws[r0*DF + f]), x, acc0);
                            if (a1) acc1 = fmaf(__ldg(&Ws[r1*DF + f]), x, acc1);
                        }
                        o0 = fmaxf(acc0, 0.f); o1 = fmaxf(acc1, 0.f);
                    }
                    res[e][k] = make_float2(a0 ? o0 : 0.f, a1 ? o1 : 0.f);
                }
            }
            __syncwarp();   // all reads of these rows done
            #pragma unroll
            for (int k = 0; k < 4; k++) {
                *(float2*)&OUT0[(grp*4 + k) * 64 + r0] = res[0][k];
                *(float2*)&OUT1[(grp*4 + k) * 64 + r0] = res[1][k];
            }
        }
        __syncwarp();

        // ---- scores for pred-less nodes (final values already) ----
        #pragma unroll 1
        for (int e = 0; e < 2; e++) {
            float* O   = e ? OUT1 : OUT0;
            float* SCB = e ? SCB1 : SCB0;
            const unsigned mbl = e ? bl1 : bl0, mbh = e ? bh1 : bh0;
            ull miss = (ull)(~mbl) | ((ull)((~mbh) & 0xffffu) << 32);
            while (miss) {
                int t = __ffsll(miss) - 1;
                miss &= miss - 1;
                float2 o = *(float2*)&O[t*64 + r0];
                float c = o.x * aw0 + o.y * aw1;
                c = warp_sum(c);
                if (lane < 4) SCB[t*4 + lane] = (lane == 0) ? c : 0.f;
            }
        }
        __syncwarp();

        // ---- reload W with x-half merge weights ----
        #pragma unroll
        for (int j = 0; j < 32; j++) {
            W[j]      = (a0 && j < 31) ? pack2(__ldg(&Wm[r0*124 + 2*j]), __ldg(&Wm[r0*124 + 2*j + 1])) : 0ull;
            W[32 + j] = (a1 && j < 31) ? pack2(__ldg(&Wm[r1*124 + 2*j]), __ldg(&Wm[r1*124 + 2*j + 1])) : 0ull;
        }

        // ================= recurrent step loop, 2 DAG streams =================
        for (int t = 1; t < NN; t++) {
            const bool h0 = mbit(bl0, bh0, t);
            const bool h1 = mbit(bl1, bh1, t);

            // ---- phase A: softmax + aggregate -> XS ----
            #pragma unroll
            for (int e = 0; e < 2; e++) {
                if (e ? !h1 : !h0) continue;
                float* O   = e ? OUT1 : OUT0;
                float* XS  = e ? XS1  : XS0;
                float* SCB = e ? SCB1 : SCB0;
                const int* PRD = e ? PRD1 : PRD0;
                int4 p = ((const int4*)PRD)[t];
                int q0 = max(p.x,0), q1 = max(p.y,0), q2 = max(p.z,0), q3 = max(p.w,0);
                float4 c0 = *(float4*)&SCB[q0*4];
                float4 c1 = *(float4*)&SCB[q1*4];
                float4 c2 = *(float4*)&SCB[q2*4];
                float4 c3 = *(float4*)&SCB[q3*4];
                float s0 = (p.x >= 0) ? (c0.x+c0.y+c0.z+c0.w) : -1e30f;
                float s1 = (p.y >= 0) ? (c1.x+c1.y+c1.z+c1.w) : -1e30f;
                float s2 = (p.z >= 0) ? (c2.x+c2.y+c2.z+c2.w) : -1e30f;
                float s3 = (p.w >= 0) ? (c3.x+c3.y+c3.z+c3.w) : -1e30f;
                float m = fmaxf(fmaxf(s0, s1), fmaxf(s2, s3));
                float e0 = (p.x >= 0) ? __expf(s0 - m) : 0.f;
                float e1 = (p.y >= 0) ? __expf(s1 - m) : 0.f;
                float e2 = (p.z >= 0) ? __expf(s2 - m) : 0.f;
                float e3 = (p.w >= 0) ? __expf(s3 - m) : 0.f;
                float inv = 1.f / (e0 + e1 + e2 + e3);
                float2 u0 = *(float2*)&O[q0*64 + r0];
                float2 u1 = *(float2*)&O[q1*64 + r0];
                float2 u2 = *(float2*)&O[q2*64 + r0];
                float2 u3 = *(float2*)&O[q3*64 + r0];
                float x0 = (e0*u0.x + e1*u1.x + e2*u2.x + e3*u3.x) * inv;
                float x1 = (e0*u0.y + e1*u1.y + e2*u2.y + e3*u3.y) * inv;
                *(float2*)&XS[r0] = make_float2(x0, x1);
            }
            __syncwarp();

            // ---- phase B: matvec + store + score partials ----
            if (h0 & h1) {
                float2 ap0 = *(float2*)&OUT0[t*64 + r0];
                float2 ap1 = *(float2*)&OUT1[t*64 + r0];
                const ulonglong2* xa = (const ulonglong2*)XS0;
                const ulonglong2* xb = (const ulonglong2*)XS1;
                ull A0=0,A1=0,A2=0,A3=0,B0=0,B1=0,B2=0,B3=0;
                ull C0=0,C1=0,C2=0,C3=0,D0=0,D1=0,D2=0,D3=0;
                #pragma unroll
                for (int i = 0; i < 8; i++) {
                    ulonglong2 u0 = xa[2*i], w0 = xa[2*i + 1];
                    ulonglong2 u1 = xb[2*i], w1 = xb[2*i + 1];
                    A0 = ffma2(W[4*i],      u0.x, A0); A1 = ffma2(W[4*i+1],    u0.y, A1);
                    A2 = ffma2(W[4*i+2],    w0.x, A2); A3 = ffma2(W[4*i+3],    w0.y, A3);
                    B0 = ffma2(W[32+4*i],   u0.x, B0); B1 = ffma2(W[32+4*i+1], u0.y, B1);
                    B2 = ffma2(W[32+4*i+2], w0.x, B2); B3 = ffma2(W[32+4*i+3], w0.y, B3);
                    C0 = ffma2(W[4*i],      u1.x, C0); C1 = ffma2(W[4*i+1],    u1.y, C1);
                    C2 = ffma2(W[4*i+2],    w1.x, C2); C3 = ffma2(W[4*i+3],    w1.y, C3);
                    D0 = ffma2(W[32+4*i],   u1.x, D0); D1 = ffma2(W[32+4*i+1], u1.y, D1);
                    D2 = ffma2(W[32+4*i+2], w1.x, D2); D3 = ffma2(W[32+4*i+3], w1.y, D3);
                }
                float sA = (lo2(A0)+hi2(A0)) + (lo2(A1)+hi2(A1)) + (lo2(A2)+hi2(A2)) + (lo2(A3)+hi2(A3));
                float sB = (lo2(B0)+hi2(B0)) + (lo2(B1)+hi2(B1)) + (lo2(B2)+hi2(B2)) + (lo2(B3)+hi2(B3));
                float sC = (lo2(C0)+hi2(C0)) + (lo2(C1)+hi2(C1)) + (lo2(C2)+hi2(C2)) + (lo2(C3)+hi2(C3));
                float sD = (lo2(D0)+hi2(D0)) + (lo2(D1)+hi2(D1)) + (lo2(D2)+hi2(D2)) + (lo2(D3)+hi2(D3));
                float v00 = fmaxf(sA + ap0.x, 0.f), v01 = fmaxf(sB + ap0.y, 0.f);
                float v10 = fmaxf(sC + ap1.x, 0.f), v11 = fmaxf(sD + ap1.y, 0.f);
                *(float2*)&OUT0[t*64 + r0] = make_float2(a0 ? v00 : 0.f, a1 ? v01 : 0.f);
                *(float2*)&OUT1[t*64 + r0] = make_float2(a0 ? v10 : 0.f, a1 ? v11 : 0.f);
                float c0 = v00 * aw0 + v01 * aw1;
                float c1 = v10 * aw0 + v11 * aw1;
                c0 = red8(c0); c1 = red8(c1);
                if ((lane & 7) == 0) {
                    SCB0[t*4 + (lane >> 3)] = c0;
                    SCB1[t*4 + (lane >> 3)] = c1;
                }
            } else if (h0 | h1) {
                float* O   = h0 ? OUT0 : OUT1;
                float* XS  = h0 ? XS0  : XS1;
                float* SCB = h0 ? SCB0 : SCB1;
                float2 ap = *(float2*)&O[t*64 + r0];
                const ulonglong2* xp = (const ulonglong2*)XS;
                ull A0=0,A1=0,A2=0,A3=0,B0=0,B1=0,B2=0,B3=0;
                #pragma unroll
                for (int i = 0; i < 8; i++) {
                    ulonglong2 u = xp[2*i], w = xp[2*i + 1];
                    A0 = ffma2(W[4*i],      u.x, A0); A1 = ffma2(W[4*i+1],    u.y, A1);
                    A2 = ffma2(W[4*i+2],    w.x, A2); A3 = ffma2(W[4*i+3],    w.y, A3);
                    B0 = ffma2(W[32+4*i],   u.x, B0); B1 = ffma2(W[32+4*i+1], u.y, B1);
                    B2 = ffma2(W[32+4*i+2], w.x, B2); B3 = ffma2(W[32+4*i+3], w.y, B3);
                }
                float sA = (lo2(A0)+hi2(A0)) + (lo2(A1)+hi2(A1)) + (lo2(A2)+hi2(A2)) + (lo2(A3)+hi2(A3));
                float sB = (lo2(B0)+hi2(B0)) + (lo2(B1)+hi2(B1)) + (lo2(B2)+hi2(B2)) + (lo2(B3)+hi2(B3));
                float v0 = fmaxf(sA + ap.x, 0.f), v1 = fmaxf(sB + ap.y, 0.f);
                *(float2*)&O[t*64 + r0] = make_float2(a0 ? v0 : 0.f, a1 ? v1 : 0.f);
                float c = v0 * aw0 + v1 * aw1;
                c = red8(c);
                if ((lane & 7) == 0) SCB[t*4 + (lane >> 3)] = c;
            }
            __syncwarp();
        }

        // ---- finalize both DAGs ----
        {
            float2 l0 = *(float2*)&OUT0[47*64 + r0];
            float2 l1 = *(float2*)&OUT1[47*64 + r0];
            *(float2*)&g_last[(size_t)d0*64 + r0] = l0;
            *(float2*)&g_last[(size_t)d1*64 + r0] = l1;
            float v0 = l0.x * dg0 + l0.y * dg1;
            float v1 = l1.x * dg0 + l1.y * dg1;
            v0 = warp_sum(v0); v1 = warp_sum(v1);
            if (lane == 0) { g_score[d0] = v0; g_score[d1] = v1; }
        }
        __syncwarp();
    }
}

// =================================================================
// k_pool_partial: deterministic partial softmax pooling over 64 DAGs
// =================================================================
__global__ void k_pool_partial() {
    __shared__ float sm_e[64];
    __shared__ float sm_red[4];
    int tid = threadIdx.x;        // 128
    int b = blockIdx.x;
    int d0 = b * 64;

    float s = (tid < 64) ? g_score[d0 + tid] : -1e30f;
    float v = s;
    #pragma unroll
    for (int o = 16; o > 0; o >>= 1) v = fmaxf(v, __shfl_xor_sync(0xffffffffu, v, o));
    if ((tid & 31) == 0 && tid < 64) sm_red[tid >> 5] = v;
    __syncthreads();
    float m = fmaxf(sm_red[0], sm_red[1]);

    float e = (tid < 64) ? __expf(s - m) : 0.f;
    if (tid < 64) sm_e[tid] = e;
    float se = warp_sum(e);
    if ((tid & 31) == 0 && tid < 64) sm_red[2 + (tid >> 5)] = se;
    __syncthreads();
    if (tid == 0) { g_partS[b] = sm_red[2] + sm_red[3]; g_partM[b] = m; }
    if (tid < DF) {
        float acc = 0.f;
        #pragma unroll 8
        for (int dd = 0; dd < 64; dd++)
            acc = fmaf(sm_e[dd], g_last[(size_t)(d0 + dd) * 64 + tid], acc);
        g_partP[b * 64 + tid] = acc;
    }
}

// =================================================================
// k_final: combine partials -> pooled -> sigmoid(W_final @ pooled + b)
// =================================================================
__global__ void k_final(const float* __restrict__ Wf, const float* __restrict__ bf,
                        float* __restrict__ out) {
    __shared__ float sw[K2B];
    __shared__ float smMax[16];
    __shared__ float smSum[16];
    __shared__ float smScalar[2];
    __shared__ float part8[8][64];
    __shared__ float pooled[64];
    int tid = threadIdx.x;        // 512
    int lane = tid & 31, warp = tid >> 5;

    float m = (tid < K2B) ? g_partM[tid] : -1e30f;
    float v = m;
    #pragma unroll
    for (int o = 16; o > 0; o >>= 1) v = fmaxf(v, __shfl_xor_sync(0xffffffffu, v, o));
    if (lane == 0) smMax[warp] = v;
    __syncthreads();
    if (tid == 0) {
        float M = smMax[0];
        #pragma unroll
        for (int w = 1; w < 16; w++) M = fmaxf(M, smMax[w]);
        smScalar[0] = M;
    }
    __syncthreads();
    float M = smScalar[0];

    float wb = (tid < K2B) ? __expf(m - M) : 0.f;
    if (tid < K2B) sw[tid] = wb;
    float ss = (tid < K2B) ? g_partS[tid] * wb : 0.f;
    ss = warp_sum(ss);
    if (lane == 0) smSum[warp] = ss;
    __syncthreads();
    if (tid == 0) {
        float S = 0.f;
        #pragma unroll
        for (int w = 0; w < 16; w++) S += smSum[w];
        smScalar[1] = 1.f / S;
    }
    __syncthreads();
    float invS = smScalar[1];

    {
        int grp = tid >> 6, gg = tid & 63;
        float acc = 0.f;
        int b0 = grp * 32;
        #pragma unroll 8
        for (int b2 = b0; b2 < b0 + 32; b2++)
            acc = fmaf(sw[b2], g_partP[b2 * 64 + gg], acc);
        part8[grp][gg] = acc;
    }
    __syncthreads();
    if (tid < DF) {
        float acc = 0.f;
        #pragma unroll
        for (int c = 0; c < 8; c++) acc += part8[c][tid];
        pooled[tid] = acc * invS;
    }
    if (tid >= DF && tid < 64) pooled[tid] = 0.f;
    __syncthreads();

    for (int o = tid; o < NCLS; o += 512) {
        float acc = bf[o];
        #pragma unroll
        for (int gg = 0; gg < DF; gg++) acc = fmaf(Wf[o * DF + gg], pooled[gg], acc);
        out[o] = 1.f / (1.f + __expf(-acc));
    }
}

// =================================================================
extern "C" void kernel_launch(void* const* d_in, const int* in_sizes, int n_in,
                              void* d_out, int out_size) {
    const float* atoms = (const float*)d_in[0];
    const int*   preds = (const int*)  d_in[1];
    const float* Ws    = (const float*)d_in[2];
    const float* bs    = (const float*)d_in[3];
    const float* Wm    = (const float*)d_in[4];
    const float* bm    = (const float*)d_in[5];
    const float* attw  = (const float*)d_in[6];
    const float* dagw  = (const float*)d_in[7];
    const float* Wf    = (const float*)d_in[8];
    const float* bf    = (const float*)d_in[9];
    float* out = (float*)d_out;

    cudaFuncSetAttribute(k_dag, cudaFuncAttributeMaxDynamicSharedMemorySize, DSM_BYTES);

    k_dag<<<296, 128, DSM_BYTES>>>(atoms, preds, Wm, bm, Ws, bs, attw, dagw);
    k_pool_partial<<<K2B, 128>>>();
    k_final<<<1, 512>>>(Wf, bf, out);
}